// round 5
// baseline (speedup 1.0000x reference)
#include <cuda_runtime.h>
#include <stdint.h>

#define B_IMGS    64
#define HW        384
#define IMG_ELEMS (HW * HW)
#define N_TOTAL   (B_IMGS * IMG_ELEMS)
#define PAD       3
#define COV_NORM  (49.0f / 48.0f)
#define N_OUT     (64.0 * 378.0 * 378.0)

#define TW        64
#define TH        32
#define IN_W      70
#define AOS_STRIDE 71   // float4 units
#define S4_STRIDE  71   // floats; 71 mod 32 = 7, gcd(7,32)=1 -> conflict-free
#define GX_TILES  6
#define GY_TILES  12
#define NBLOCKS   (GX_TILES * GY_TILES * B_IMGS)

#define MAX_BLOCKS 256

__device__ double       g_sum;
__device__ unsigned int g_ticket;
__device__ float        g_blockmax[MAX_BLOCKS];

// ---------------------------------------------------------------------------
__global__ __launch_bounds__(256)
void prep_kernel(const float* __restrict__ gt) {
    if (blockIdx.x == 0 && threadIdx.x == 0) { g_sum = 0.0; g_ticket = 0u; }

    const float4* v = reinterpret_cast<const float4*>(gt);
    const int n4 = N_TOTAL / 4;
    float m = 0.0f;
    for (int i = blockIdx.x * 256 + threadIdx.x; i < n4; i += MAX_BLOCKS * 256) {
        float4 x = v[i];
        m = fmaxf(m, fmaxf(fmaxf(x.x, x.y), fmaxf(x.z, x.w)));
    }
    #pragma unroll
    for (int o = 16; o; o >>= 1) m = fmaxf(m, __shfl_xor_sync(0xffffffffu, m, o));
    __shared__ float smax[8];
    int lane = threadIdx.x & 31, wid = threadIdx.x >> 5;
    if (lane == 0) smax[wid] = m;
    __syncthreads();
    if (wid == 0) {
        m = (lane < 8) ? smax[lane] : 0.0f;
        #pragma unroll
        for (int o = 4; o; o >>= 1) m = fmaxf(m, __shfl_xor_sync(0xffffffffu, m, o));
        if (lane == 0) g_blockmax[blockIdx.x] = m;
    }
}

// ---------------------------------------------------------------------------
// Phase A: 3 row-chunks per tile (210 threads). Each thread owns one input
// column within one chunk, streams rows with a 7-row rolling register window,
// writes 5-channel vertical box sums to shared.
// Phase B: horizontal rolling window over shared sums + SSIM.
template <bool EDGE>
__device__ __forceinline__ void tile_work(
    const float* __restrict__ gbase, const float* __restrict__ pbase,
    int bx, int by, int tid,
    float4* aos, float* s4p, float* smaxv_p, float* local_out)
{
    const int row0 = by * TH;
    // ---- Phase A ----
    if (tid < 3 * IN_W) {
        const int chunk = tid / IN_W;               // 0..2
        const int c     = tid - chunk * IN_W;       // 0..69
        const int o0    = chunk * 11;
        const int nout  = (chunk == 2) ? 10 : 11;

        float g[7], p[7];
        float s0 = 0.f, s1 = 0.f, s2 = 0.f, s3 = 0.f, s4 = 0.f;

        if (!EDGE) {
            const float* gp = gbase + (row0 + o0) * HW + (bx * TW + c);
            const float* pp = pbase + (row0 + o0) * HW + (bx * TW + c);
            #pragma unroll
            for (int i = 0; i < 6; i++) {
                float a = __ldg(gp); float b = __ldg(pp);
                gp += HW; pp += HW;
                g[i] = a; p[i] = b;
                s0 += a; s1 += b;
                s2 = fmaf(a, a, s2); s3 = fmaf(b, b, s3); s4 = fmaf(a, b, s4);
            }
            #pragma unroll
            for (int j = 0; j < 11; j++) {
                int slot = (6 + j) % 7;
                float a = __ldg(gp); float b = __ldg(pp);
                gp += HW; pp += HW;
                g[slot] = a; p[slot] = b;
                s0 += a; s1 += b;
                s2 = fmaf(a, a, s2); s3 = fmaf(b, b, s3); s4 = fmaf(a, b, s4);
                if (j < nout) {
                    aos[(o0 + j) * AOS_STRIDE + c] = make_float4(s0, s1, s2, s3);
                    s4p[(o0 + j) * S4_STRIDE + c] = s4;
                }
                int os = j % 7;
                float ga = g[os], pa = p[os];
                s0 -= ga; s1 -= pa;
                s2 -= ga * ga; s3 -= pa * pa; s4 -= ga * pa;
            }
        } else {
            const int gx = min(bx * TW + c, HW - 1);
            const float* gp = gbase + gx;
            const float* pp = pbase + gx;
            const int rb = row0 + o0;
            #pragma unroll
            for (int i = 0; i < 6; i++) {
                int gy = min(rb + i, HW - 1);
                float a = __ldg(gp + gy * HW); float b = __ldg(pp + gy * HW);
                g[i] = a; p[i] = b;
                s0 += a; s1 += b;
                s2 = fmaf(a, a, s2); s3 = fmaf(b, b, s3); s4 = fmaf(a, b, s4);
            }
            #pragma unroll
            for (int j = 0; j < 11; j++) {
                int slot = (6 + j) % 7;
                int gy = min(rb + 6 + j, HW - 1);
                float a = __ldg(gp + gy * HW); float b = __ldg(pp + gy * HW);
                g[slot] = a; p[slot] = b;
                s0 += a; s1 += b;
                s2 = fmaf(a, a, s2); s3 = fmaf(b, b, s3); s4 = fmaf(a, b, s4);
                if (j < nout) {
                    aos[(o0 + j) * AOS_STRIDE + c] = make_float4(s0, s1, s2, s3);
                    s4p[(o0 + j) * S4_STRIDE + c] = s4;
                }
                int os = j % 7;
                float ga = g[os], pa = p[os];
                s0 -= ga; s1 -= pa;
                s2 -= ga * ga; s3 -= pa * pa; s4 -= ga * pa;
            }
        }
    } else if (tid >= 224) {
        // warp 7: finish the global max reduction while others load
        int lane = tid - 224;
        float m = 0.0f;
        #pragma unroll
        for (int i = 0; i < MAX_BLOCKS / 32; i++)
            m = fmaxf(m, g_blockmax[lane + 32 * i]);
        #pragma unroll
        for (int o = 16; o; o >>= 1) m = fmaxf(m, __shfl_xor_sync(0xffffffffu, m, o));
        if (lane == 0) *smaxv_p = m;
    }
    __syncthreads();

    // ---- Phase B ----
    const float R  = *smaxv_p;
    const float C1 = (0.01f * R) * (0.01f * R);
    const float C2 = (0.03f * R) * (0.03f * R);
    const float inv = 1.0f / 49.0f;

    const int seg = tid >> 5;
    const int row = tid & 31;
    const int c0  = seg * 8;
    const int abase = row * AOS_STRIDE + c0;
    const int sbase = row * S4_STRIDE  + c0;

    const bool rowvalid = EDGE ? ((PAD + by * TH + row) <= HW - 1 - PAD) : true;
    const int ox0 = PAD + bx * TW + c0;

    float4 q[7];
    float  r4[7];
    float4 s = make_float4(0.f, 0.f, 0.f, 0.f);
    float  t4 = 0.f;
    #pragma unroll
    for (int i = 0; i < 6; i++) {
        float4 v = aos[abase + i];
        float  u = s4p[sbase + i];
        q[i] = v; r4[i] = u;
        s.x += v.x; s.y += v.y; s.z += v.z; s.w += v.w;
        t4 += u;
    }

    float local = 0.0f;
    #pragma unroll
    for (int k = 0; k < 8; k++) {
        int slot = (6 + k) % 7;
        float4 v = aos[abase + 6 + k];
        float  u = s4p[sbase + 6 + k];
        q[slot] = v; r4[slot] = u;
        s.x += v.x; s.y += v.y; s.z += v.z; s.w += v.w;
        t4 += u;

        bool valid = EDGE ? (rowvalid && (ox0 + k) <= HW - 1 - PAD) : true;
        if (valid) {
            float ux = s.x * inv, uy = s.y * inv;
            float uxx = s.z * inv - ux * ux;
            float uyy = s.w * inv - uy * uy;
            float uxy = t4  * inv - ux * uy;
            float vx = COV_NORM * uxx, vy = COV_NORM * uyy, vxy = COV_NORM * uxy;
            float num = (2.0f * ux * uy + C1) * (2.0f * vxy + C2);
            float den = (ux * ux + uy * uy + C1) * (vx + vy + C2);
            local += __fdividef(num, den);
        }

        int os = k % 7;
        float4 w = q[os];
        s.x -= w.x; s.y -= w.y; s.z -= w.z; s.w -= w.w;
        t4 -= r4[os];
    }
    *local_out = local;
}

__global__ __launch_bounds__(256, 4)
void ssim_kernel(const float* __restrict__ gt, const float* __restrict__ pred,
                 float* __restrict__ out) {
    __shared__ float4 aos[TH * AOS_STRIDE];
    __shared__ float  s4p[TH * S4_STRIDE];
    __shared__ float  sred[8];
    __shared__ float  smaxv;

    const int tid = threadIdx.x;
    const int bx = blockIdx.x, by = blockIdx.y, img = blockIdx.z;

    const float* gbase = gt   + img * IMG_ELEMS;
    const float* pbase = pred + img * IMG_ELEMS;

    float local;
    if (bx < GX_TILES - 1 && by < GY_TILES - 1)
        tile_work<false>(gbase, pbase, bx, by, tid, aos, s4p, &smaxv, &local);
    else
        tile_work<true >(gbase, pbase, bx, by, tid, aos, s4p, &smaxv, &local);

    // ---- reduction: warp shuffle -> 8 floats -> thread 0 ----
    #pragma unroll
    for (int o = 16; o; o >>= 1) local += __shfl_xor_sync(0xffffffffu, local, o);
    if ((tid & 31) == 0) sred[tid >> 5] = local;
    __syncthreads();
    if (tid == 0) {
        float v = sred[0] + sred[1] + sred[2] + sred[3]
                + sred[4] + sred[5] + sred[6] + sred[7];
        atomicAdd(&g_sum, (double)v);
        __threadfence();
        unsigned t = atomicAdd(&g_ticket, 1u);
        if (t == NBLOCKS - 1) {
            double total = atomicAdd(&g_sum, 0.0);
            out[0] = (float)(total / N_OUT);
        }
    }
}

// ---------------------------------------------------------------------------
extern "C" void kernel_launch(void* const* d_in, const int* in_sizes, int n_in,
                              void* d_out, int out_size) {
    const float* gt   = (const float*)d_in[0];
    const float* pred = (const float*)d_in[1];
    float* out = (float*)d_out;

    prep_kernel<<<MAX_BLOCKS, 256>>>(gt);
    dim3 grid(GX_TILES, GY_TILES, B_IMGS);
    ssim_kernel<<<grid, 256>>>(gt, pred, out);
}

// round 6
// speedup vs baseline: 1.0508x; 1.0508x over previous
#include <cuda_runtime.h>
#include <stdint.h>

#define B_IMGS    64
#define HW        384
#define IMG_ELEMS (HW * HW)
#define N_TOTAL   (B_IMGS * IMG_ELEMS)
#define PAD       3
#define COV_NORM  (49.0f / 48.0f)
#define N_OUT     (64.0 * 378.0 * 378.0)

#define TW        64
#define TH        32
#define IN_W      70
#define AOS_STRIDE 71   // float4 units; 284 words mod 128 -> 32 distinct, conflict-free
#define S4_STRIDE  71   // floats; gcd(7,32)=1 -> conflict-free
#define GX_TILES  6
#define GY_TILES  12
#define NBLOCKS   (GX_TILES * GY_TILES * B_IMGS)

#define MAX_BLOCKS 256

__device__ double       g_sum;
__device__ unsigned int g_ticket;
__device__ float        g_blockmax[MAX_BLOCKS];

// ---------------------------------------------------------------------------
__global__ __launch_bounds__(256)
void prep_kernel(const float* __restrict__ gt) {
    if (blockIdx.x == 0 && threadIdx.x == 0) { g_sum = 0.0; g_ticket = 0u; }

    const float4* v = reinterpret_cast<const float4*>(gt);
    const int n4 = N_TOTAL / 4;
    float m = 0.0f;
    for (int i = blockIdx.x * 256 + threadIdx.x; i < n4; i += MAX_BLOCKS * 256) {
        float4 x = v[i];
        m = fmaxf(m, fmaxf(fmaxf(x.x, x.y), fmaxf(x.z, x.w)));
    }
    #pragma unroll
    for (int o = 16; o; o >>= 1) m = fmaxf(m, __shfl_xor_sync(0xffffffffu, m, o));
    __shared__ float smax[8];
    int lane = threadIdx.x & 31, wid = threadIdx.x >> 5;
    if (lane == 0) smax[wid] = m;
    __syncthreads();
    if (wid == 0) {
        m = (lane < 8) ? smax[lane] : 0.0f;
        #pragma unroll
        for (int o = 4; o; o >>= 1) m = fmaxf(m, __shfl_xor_sync(0xffffffffu, m, o));
        if (lane == 0) g_blockmax[blockIdx.x] = m;
    }
}

// ---------------------------------------------------------------------------
template <bool EDGE>
__device__ __forceinline__ void tile_work(
    const float* __restrict__ gbase, const float* __restrict__ pbase,
    int bx, int by, int tid,
    float4* aos, float* s4p, float* smaxv_p, float* local_out)
{
    const int row0 = by * TH;
    // ---- Phase A: vertical 7-row box sums (3 row-chunks, 210 threads) ----
    if (tid < 3 * IN_W) {
        const int chunk = tid / IN_W;               // 0..2
        const int c     = tid - chunk * IN_W;       // 0..69
        const int o0    = chunk * 11;
        const int nout  = (chunk == 2) ? 10 : 11;

        float g[7], p[7];
        float s0 = 0.f, s1 = 0.f, s2 = 0.f, s3 = 0.f, s4 = 0.f;

        if (!EDGE) {
            const float* gp = gbase + (row0 + o0) * HW + (bx * TW + c);
            const float* pp = pbase + (row0 + o0) * HW + (bx * TW + c);
            #pragma unroll
            for (int i = 0; i < 6; i++) {
                float a = __ldg(gp); float b = __ldg(pp);
                gp += HW; pp += HW;
                g[i] = a; p[i] = b;
                s0 += a; s1 += b;
                s2 = fmaf(a, a, s2); s3 = fmaf(b, b, s3); s4 = fmaf(a, b, s4);
            }
            #pragma unroll
            for (int j = 0; j < 11; j++) {
                int slot = (6 + j) % 7;
                float a = __ldg(gp); float b = __ldg(pp);
                gp += HW; pp += HW;
                g[slot] = a; p[slot] = b;
                s0 += a; s1 += b;
                s2 = fmaf(a, a, s2); s3 = fmaf(b, b, s3); s4 = fmaf(a, b, s4);
                if (j < nout) {
                    aos[(o0 + j) * AOS_STRIDE + c] = make_float4(s0, s1, s2, s3);
                    s4p[(o0 + j) * S4_STRIDE + c] = s4;
                }
                int os = j % 7;
                float ga = g[os], pa = p[os];
                s0 -= ga; s1 -= pa;
                s2 -= ga * ga; s3 -= pa * pa; s4 -= ga * pa;
            }
        } else {
            const int gx = min(bx * TW + c, HW - 1);
            const float* gp = gbase + gx;
            const float* pp = pbase + gx;
            const int rb = row0 + o0;
            #pragma unroll
            for (int i = 0; i < 6; i++) {
                int gy = min(rb + i, HW - 1);
                float a = __ldg(gp + gy * HW); float b = __ldg(pp + gy * HW);
                g[i] = a; p[i] = b;
                s0 += a; s1 += b;
                s2 = fmaf(a, a, s2); s3 = fmaf(b, b, s3); s4 = fmaf(a, b, s4);
            }
            #pragma unroll
            for (int j = 0; j < 11; j++) {
                int slot = (6 + j) % 7;
                int gy = min(rb + 6 + j, HW - 1);
                float a = __ldg(gp + gy * HW); float b = __ldg(pp + gy * HW);
                g[slot] = a; p[slot] = b;
                s0 += a; s1 += b;
                s2 = fmaf(a, a, s2); s3 = fmaf(b, b, s3); s4 = fmaf(a, b, s4);
                if (j < nout) {
                    aos[(o0 + j) * AOS_STRIDE + c] = make_float4(s0, s1, s2, s3);
                    s4p[(o0 + j) * S4_STRIDE + c] = s4;
                }
                int os = j % 7;
                float ga = g[os], pa = p[os];
                s0 -= ga; s1 -= pa;
                s2 -= ga * ga; s3 -= pa * pa; s4 -= ga * pa;
            }
        }
    } else if (tid >= 224) {
        int lane = tid - 224;
        float m = 0.0f;
        #pragma unroll
        for (int i = 0; i < MAX_BLOCKS / 32; i++)
            m = fmaxf(m, g_blockmax[lane + 32 * i]);
        #pragma unroll
        for (int o = 16; o; o >>= 1) m = fmaxf(m, __shfl_xor_sync(0xffffffffu, m, o));
        if (lane == 0) *smaxv_p = m;
    }
    __syncthreads();

    // ---- Phase B: horizontal 7-col sums; subtract operand re-read from smem
    //      (no rolling register arrays -> low register pressure -> 5 CTAs/SM)
    const float R  = *smaxv_p;
    const float C1 = (0.01f * R) * (0.01f * R);
    const float C2 = (0.03f * R) * (0.03f * R);
    const float inv = 1.0f / 49.0f;

    const int seg = tid >> 5;
    const int row = tid & 31;
    const int c0  = seg * 8;
    const int abase = row * AOS_STRIDE + c0;
    const int sbase = row * S4_STRIDE  + c0;

    const bool rowvalid = EDGE ? ((PAD + by * TH + row) <= HW - 1 - PAD) : true;
    const int ox0 = PAD + bx * TW + c0;

    float4 s = make_float4(0.f, 0.f, 0.f, 0.f);
    float  t4 = 0.f;
    #pragma unroll
    for (int i = 0; i < 6; i++) {
        float4 v = aos[abase + i];
        float  u = s4p[sbase + i];
        s.x += v.x; s.y += v.y; s.z += v.z; s.w += v.w;
        t4 += u;
    }

    float local = 0.0f;
    #pragma unroll
    for (int k = 0; k < 8; k++) {
        float4 v = aos[abase + 6 + k];
        float  u = s4p[sbase + 6 + k];
        s.x += v.x; s.y += v.y; s.z += v.z; s.w += v.w;
        t4 += u;

        bool valid = EDGE ? (rowvalid && (ox0 + k) <= HW - 1 - PAD) : true;
        if (valid) {
            float ux = s.x * inv, uy = s.y * inv;
            float uxx = s.z * inv - ux * ux;
            float uyy = s.w * inv - uy * uy;
            float uxy = t4  * inv - ux * uy;
            float vx = COV_NORM * uxx, vy = COV_NORM * uyy, vxy = COV_NORM * uxy;
            float num = (2.0f * ux * uy + C1) * (2.0f * vxy + C2);
            float den = (ux * ux + uy * uy + C1) * (vx + vy + C2);
            local += __fdividef(num, den);
        }

        float4 w = aos[abase + k];       // re-read subtract operand from smem
        float  uw = s4p[sbase + k];
        s.x -= w.x; s.y -= w.y; s.z -= w.z; s.w -= w.w;
        t4 -= uw;
    }
    *local_out = local;
}

__global__ __launch_bounds__(256, 5)
void ssim_kernel(const float* __restrict__ gt, const float* __restrict__ pred,
                 float* __restrict__ out) {
    __shared__ float4 aos[TH * AOS_STRIDE];
    __shared__ float  s4p[TH * S4_STRIDE];
    __shared__ float  sred[8];
    __shared__ float  smaxv;

    const int tid = threadIdx.x;
    const int bx = blockIdx.x, by = blockIdx.y, img = blockIdx.z;

    const float* gbase = gt   + img * IMG_ELEMS;
    const float* pbase = pred + img * IMG_ELEMS;

    float local;
    if (bx < GX_TILES - 1 && by < GY_TILES - 1)
        tile_work<false>(gbase, pbase, bx, by, tid, aos, s4p, &smaxv, &local);
    else
        tile_work<true >(gbase, pbase, bx, by, tid, aos, s4p, &smaxv, &local);

    #pragma unroll
    for (int o = 16; o; o >>= 1) local += __shfl_xor_sync(0xffffffffu, local, o);
    if ((tid & 31) == 0) sred[tid >> 5] = local;
    __syncthreads();
    if (tid == 0) {
        float v = sred[0] + sred[1] + sred[2] + sred[3]
                + sred[4] + sred[5] + sred[6] + sred[7];
        atomicAdd(&g_sum, (double)v);
        __threadfence();
        unsigned t = atomicAdd(&g_ticket, 1u);
        if (t == NBLOCKS - 1) {
            double total = atomicAdd(&g_sum, 0.0);
            out[0] = (float)(total / N_OUT);
        }
    }
}

// ---------------------------------------------------------------------------
extern "C" void kernel_launch(void* const* d_in, const int* in_sizes, int n_in,
                              void* d_out, int out_size) {
    const float* gt   = (const float*)d_in[0];
    const float* pred = (const float*)d_in[1];
    float* out = (float*)d_out;

    prep_kernel<<<MAX_BLOCKS, 256>>>(gt);
    dim3 grid(GX_TILES, GY_TILES, B_IMGS);
    ssim_kernel<<<grid, 256>>>(gt, pred, out);
}

// round 7
// speedup vs baseline: 1.1089x; 1.0553x over previous
#include <cuda_runtime.h>
#include <stdint.h>

#define B_IMGS    64
#define HW        384
#define IMG_ELEMS (HW * HW)
#define N_TOTAL   (B_IMGS * IMG_ELEMS)
#define PAD       3
#define COV_NORM  (49.0f / 48.0f)
#define N_OUT     (64.0 * 378.0 * 378.0)

#define TW        64
#define TH        32
#define IN_W      70
#define AOS_STRIDE 71   // float4 units; conflict-free (28r mod 32 distinct)
#define GX_TILES  6
#define GY_TILES  12
#define NBLOCKS   (GX_TILES * GY_TILES * B_IMGS)

#define MAX_BLOCKS 256

__device__ double       g_sum;
__device__ unsigned int g_ticket;
__device__ float        g_blockmax[MAX_BLOCKS];

// ---------------------------------------------------------------------------
__global__ __launch_bounds__(256)
void prep_kernel(const float* __restrict__ gt) {
    if (blockIdx.x == 0 && threadIdx.x == 0) { g_sum = 0.0; g_ticket = 0u; }

    const float4* v = reinterpret_cast<const float4*>(gt);
    const int n4 = N_TOTAL / 4;
    float m = 0.0f;
    for (int i = blockIdx.x * 256 + threadIdx.x; i < n4; i += MAX_BLOCKS * 256) {
        float4 x = v[i];
        m = fmaxf(m, fmaxf(fmaxf(x.x, x.y), fmaxf(x.z, x.w)));
    }
    #pragma unroll
    for (int o = 16; o; o >>= 1) m = fmaxf(m, __shfl_xor_sync(0xffffffffu, m, o));
    __shared__ float smax[8];
    int lane = threadIdx.x & 31, wid = threadIdx.x >> 5;
    if (lane == 0) smax[wid] = m;
    __syncthreads();
    if (wid == 0) {
        m = (lane < 8) ? smax[lane] : 0.0f;
        #pragma unroll
        for (int o = 4; o; o >>= 1) m = fmaxf(m, __shfl_xor_sync(0xffffffffu, m, o));
        if (lane == 0) g_blockmax[blockIdx.x] = m;
    }
}

// ---------------------------------------------------------------------------
// 4-channel vertical box sums: (sum a, sum b, sum a^2+b^2, sum ab).
// Phase A: 3 row-chunks x 70 columns (210 threads), rolling 7-row window.
// Phase B: horizontal rolling sums, subtract operand re-read from smem.
template <bool EDGE>
__device__ __forceinline__ void tile_work(
    const float* __restrict__ gbase, const float* __restrict__ pbase,
    int bx, int by, int tid,
    float4* aos, float* smaxv_p, float* local_out)
{
    const int row0 = by * TH;
    // ---- Phase A ----
    if (tid < 3 * IN_W) {
        const int chunk = tid / IN_W;               // 0..2
        const int c     = tid - chunk * IN_W;       // 0..69
        const int o0    = chunk * 11;
        const int nout  = (chunk == 2) ? 10 : 11;

        float g[7], p[7];
        float s0 = 0.f, s1 = 0.f, s23 = 0.f, s4 = 0.f;

        if (!EDGE) {
            const float* gp = gbase + (row0 + o0) * HW + (bx * TW + c);
            const float* pp = pbase + (row0 + o0) * HW + (bx * TW + c);
            #pragma unroll
            for (int i = 0; i < 6; i++) {
                float a = __ldg(gp); float b = __ldg(pp);
                gp += HW; pp += HW;
                g[i] = a; p[i] = b;
                s0 += a; s1 += b;
                s23 = fmaf(a, a, s23); s23 = fmaf(b, b, s23);
                s4  = fmaf(a, b, s4);
            }
            #pragma unroll
            for (int j = 0; j < 11; j++) {
                int slot = (6 + j) % 7;
                float a = __ldg(gp); float b = __ldg(pp);
                gp += HW; pp += HW;
                g[slot] = a; p[slot] = b;
                s0 += a; s1 += b;
                s23 = fmaf(a, a, s23); s23 = fmaf(b, b, s23);
                s4  = fmaf(a, b, s4);
                if (j < nout)
                    aos[(o0 + j) * AOS_STRIDE + c] = make_float4(s0, s1, s23, s4);
                int os = j % 7;
                float ga = g[os], pa = p[os];
                s0 -= ga; s1 -= pa;
                s23 -= fmaf(ga, ga, pa * pa);
                s4  -= ga * pa;
            }
        } else {
            const int gx = min(bx * TW + c, HW - 1);
            const float* gp = gbase + gx;
            const float* pp = pbase + gx;
            const int rb = row0 + o0;
            #pragma unroll
            for (int i = 0; i < 6; i++) {
                int gy = min(rb + i, HW - 1);
                float a = __ldg(gp + gy * HW); float b = __ldg(pp + gy * HW);
                g[i] = a; p[i] = b;
                s0 += a; s1 += b;
                s23 = fmaf(a, a, s23); s23 = fmaf(b, b, s23);
                s4  = fmaf(a, b, s4);
            }
            #pragma unroll
            for (int j = 0; j < 11; j++) {
                int slot = (6 + j) % 7;
                int gy = min(rb + 6 + j, HW - 1);
                float a = __ldg(gp + gy * HW); float b = __ldg(pp + gy * HW);
                g[slot] = a; p[slot] = b;
                s0 += a; s1 += b;
                s23 = fmaf(a, a, s23); s23 = fmaf(b, b, s23);
                s4  = fmaf(a, b, s4);
                if (j < nout)
                    aos[(o0 + j) * AOS_STRIDE + c] = make_float4(s0, s1, s23, s4);
                int os = j % 7;
                float ga = g[os], pa = p[os];
                s0 -= ga; s1 -= pa;
                s23 -= fmaf(ga, ga, pa * pa);
                s4  -= ga * pa;
            }
        }
    } else if (tid >= 224) {
        int lane = tid - 224;
        float m = 0.0f;
        #pragma unroll
        for (int i = 0; i < MAX_BLOCKS / 32; i++)
            m = fmaxf(m, g_blockmax[lane + 32 * i]);
        #pragma unroll
        for (int o = 16; o; o >>= 1) m = fmaxf(m, __shfl_xor_sync(0xffffffffu, m, o));
        if (lane == 0) *smaxv_p = m;
    }
    __syncthreads();

    // ---- Phase B ----
    const float R  = *smaxv_p;
    const float C1 = (0.01f * R) * (0.01f * R);
    const float C2 = (0.03f * R) * (0.03f * R);
    const float inv = 1.0f / 49.0f;

    const int seg = tid >> 5;
    const int row = tid & 31;
    const int c0  = seg * 8;
    const int abase = row * AOS_STRIDE + c0;

    const bool rowvalid = EDGE ? ((PAD + by * TH + row) <= HW - 1 - PAD) : true;
    const int ox0 = PAD + bx * TW + c0;

    float4 s = make_float4(0.f, 0.f, 0.f, 0.f);
    #pragma unroll
    for (int i = 0; i < 6; i++) {
        float4 v = aos[abase + i];
        s.x += v.x; s.y += v.y; s.z += v.z; s.w += v.w;
    }

    float local = 0.0f;
    #pragma unroll
    for (int k = 0; k < 8; k++) {
        float4 v = aos[abase + 6 + k];
        s.x += v.x; s.y += v.y; s.z += v.z; s.w += v.w;

        bool valid = EDGE ? (rowvalid && (ox0 + k) <= HW - 1 - PAD) : true;
        if (valid) {
            float ux = s.x * inv, uy = s.y * inv;
            float sumvar = s.z * inv - ux * ux - uy * uy;   // uxx + uyy
            float uxy    = s.w * inv - ux * uy;
            float num = (2.0f * ux * uy + C1) * (2.0f * COV_NORM * uxy + C2);
            float den = (ux * ux + uy * uy + C1) * (COV_NORM * sumvar + C2);
            local += __fdividef(num, den);
        }

        float4 w = aos[abase + k];       // re-read subtract operand
        s.x -= w.x; s.y -= w.y; s.z -= w.z; s.w -= w.w;
    }
    *local_out = local;
}

__global__ __launch_bounds__(256, 6)
void ssim_kernel(const float* __restrict__ gt, const float* __restrict__ pred,
                 float* __restrict__ out) {
    __shared__ float4 aos[TH * AOS_STRIDE];
    __shared__ float  sred[8];
    __shared__ float  smaxv;

    const int tid = threadIdx.x;
    const int bx = blockIdx.x, by = blockIdx.y, img = blockIdx.z;

    const float* gbase = gt   + img * IMG_ELEMS;
    const float* pbase = pred + img * IMG_ELEMS;

    float local;
    if (bx < GX_TILES - 1 && by < GY_TILES - 1)
        tile_work<false>(gbase, pbase, bx, by, tid, aos, &smaxv, &local);
    else
        tile_work<true >(gbase, pbase, bx, by, tid, aos, &smaxv, &local);

    #pragma unroll
    for (int o = 16; o; o >>= 1) local += __shfl_xor_sync(0xffffffffu, local, o);
    if ((tid & 31) == 0) sred[tid >> 5] = local;
    __syncthreads();
    if (tid == 0) {
        float v = sred[0] + sred[1] + sred[2] + sred[3]
                + sred[4] + sred[5] + sred[6] + sred[7];
        atomicAdd(&g_sum, (double)v);
        __threadfence();
        unsigned t = atomicAdd(&g_ticket, 1u);
        if (t == NBLOCKS - 1) {
            double total = atomicAdd(&g_sum, 0.0);
            out[0] = (float)(total / N_OUT);
        }
    }
}

// ---------------------------------------------------------------------------
extern "C" void kernel_launch(void* const* d_in, const int* in_sizes, int n_in,
                              void* d_out, int out_size) {
    const float* gt   = (const float*)d_in[0];
    const float* pred = (const float*)d_in[1];
    float* out = (float*)d_out;

    prep_kernel<<<MAX_BLOCKS, 256>>>(gt);
    dim3 grid(GX_TILES, GY_TILES, B_IMGS);
    ssim_kernel<<<grid, 256>>>(gt, pred, out);
}